// round 12
// baseline (speedup 1.0000x reference)
#include <cuda_runtime.h>
#include <cuda_fp16.h>
#include <cstdint>

#define NN 100000
#define NE 1600000
#define FDIM 128
#define NCLS 40

// ------------------------- device scratch (no allocs) -----------------------
__device__ __align__(16) __half g_mh[(size_t)NN * FDIM];   // pool messages (fp16)
__device__ __align__(16) __half g_aggh[(size_t)NN * FDIM]; // segment-max agg (fp16)
__device__ __align__(16) __half g_hh[(size_t)NN * FDIM];   // layer-1 hidden (fp16)
__device__ __align__(16) __half g_xh[(size_t)NN * FDIM];   // fp16 in_feat
__device__ __align__(16) __half g_wh[75776];               // fp16 weights (6 matrices)
__device__ int   g_deg[NN];
__device__ int   g_off[NN + 1];  // tile-local exclusive after scanA; local inclusive after scatter
__device__ int   g_csr[NE];
__device__ int   g_part[128];    // scan tile partials (exclusive after scanB)

// weight offsets inside g_wh
#define WR_PW1 0
#define WR_SW1 16384
#define WR_NW1 32768
#define WR_PW2 49152
#define WR_SW2 65536
#define WR_NW2 70656

// ------------------------- PTX helpers --------------------------------------
__device__ __forceinline__ uint32_t smem_to_u32(const void* p) {
    uint32_t a;
    asm("{ .reg .u64 t; cvta.to.shared.u64 t, %1; cvt.u32.u64 %0, t; }"
        : "=r"(a) : "l"(p));
    return a;
}
#define CPASYNC16(sa, ga, sz) \
    asm volatile("cp.async.cg.shared.global [%0], [%1], 16, %2;" \
                 :: "r"(sa), "l"(ga), "r"(sz))
#define CPCOMMIT() asm volatile("cp.async.commit_group;" ::: "memory")
#define CPWAIT(N)  asm volatile("cp.async.wait_group %0;" :: "n"(N) : "memory")

// m16n8k16 fp16 HMMA, f32 accum. Base PTX (sm_80+): compiles at compute_103.
__device__ __forceinline__ void mma_f16(float* d, const uint32_t* a, const uint32_t* b)
{
    asm volatile(
        "mma.sync.aligned.m16n8k16.row.col.f32.f16.f16.f32 "
        "{%0,%1,%2,%3}, {%4,%5,%6,%7}, {%8,%9}, {%0,%1,%2,%3};"
        : "+f"(d[0]), "+f"(d[1]), "+f"(d[2]), "+f"(d[3])
        : "r"(a[0]), "r"(a[1]), "r"(a[2]), "r"(a[3]),
          "r"(b[0]), "r"(b[1]));
}

__device__ __forceinline__ uint32_t hmax2u(uint32_t a, uint32_t b)
{
    __half2 r = __hmax2(*(__half2*)&a, *(__half2*)&b);
    return *(uint32_t*)&r;
}

#define KP 72   // padded smem k stride (halves)

// ------------------------- fp16 warp-MMA GEMM (generic) ----------------------
template<int BN, bool DUAL, bool OUT_HALF>
__global__ void __launch_bounds__(256, 2) mma_gemm_kernel(
    const __half* __restrict__ X0, const __half* __restrict__ X1,
    const __half* __restrict__ W0, const __half* __restrict__ W1,
    const float* __restrict__ b0, const float* __restrict__ b1,
    void* __restrict__ out_v, int n, int fout, int do_relu)
{
    constexpr int NF = BN / 16;
    extern __shared__ __align__(16) __half smem_h[];
    __half* As = smem_h;                     // [2][128*KP]
    __half* Bs = smem_h + 2 * 128 * KP;      // [2][BN*KP]
    float* bias_s = (float*)(smem_h + 2 * 128 * KP + 2 * BN * KP);

    const int tid   = threadIdx.x;
    const int lane  = tid & 31, wid = tid >> 5;
    const int g     = lane >> 2, tig = lane & 3;
    const int m_base = (wid & 3) * 32;
    const int n_base = (wid >> 2) * (BN / 2);
    const int row0  = blockIdx.x * 128;
    const uint32_t sbA = smem_to_u32(smem_h);
    const uint32_t sbB = sbA + 2 * 128 * KP * 2;

    if (tid < BN) {
        float bv = 0.f;
        if (tid < fout) { bv = b0[tid]; if (b1 != nullptr) bv += b1[tid]; }
        bias_s[tid] = bv;
    }

    auto load_chunk = [&](int c, int buf) {
        const __half* X = (c < 2) ? X0 : X1;
        const __half* W = (c < 2) ? W0 : W1;
        const int kc = (c & 1) * 64;
        #pragma unroll
        for (int i = 0; i < 4; i++) {
            int lin = i * 256 + tid;
            int r = lin >> 3, s = lin & 7;
            int gr = row0 + r;
            int ok = (gr < n);
            const __half* src = X + (size_t)(ok ? gr : 0) * 128 + kc + s * 8;
            uint32_t sa = sbA + (uint32_t)(buf * 128 * KP + r * KP + s * 8) * 2;
            CPASYNC16(sa, src, ok ? 16 : 0);
        }
        #pragma unroll
        for (int i = 0; i < (BN * 8 + 255) / 256; i++) {
            int lin = i * 256 + tid;
            if (lin < BN * 8) {
                int r = lin >> 3, s = lin & 7;
                int ok = (r < fout);
                const __half* src = W + (size_t)(ok ? r : 0) * 128 + kc + s * 8;
                uint32_t sa = sbB + (uint32_t)(buf * BN * KP + r * KP + s * 8) * 2;
                CPASYNC16(sa, src, ok ? 16 : 0);
            }
        }
        CPCOMMIT();
    };

    float acc[2][NF][4];
    #pragma unroll
    for (int mt = 0; mt < 2; mt++)
        #pragma unroll
        for (int f = 0; f < NF; f++)
            #pragma unroll
            for (int j = 0; j < 4; j++) acc[mt][f][j] = 0.f;

    const int nch = DUAL ? 4 : 2;
    load_chunk(0, 0);
    load_chunk(1, 1);

    for (int c = 0; c < nch; c++) {
        if (c + 1 < nch) { CPWAIT(1); } else { CPWAIT(0); }
        __syncthreads();
        const int buf = c & 1;
        const __half* Ab = As + buf * 128 * KP;
        const __half* Bb = Bs + buf * BN * KP;
        #pragma unroll
        for (int kk = 0; kk < 64; kk += 16) {
            uint32_t afr[2][4];
            #pragma unroll
            for (int mt = 0; mt < 2; mt++) {
                int rb = m_base + mt * 16 + g;
                afr[mt][0] = *(const uint32_t*)&Ab[(rb)     * KP + kk + 2 * tig];
                afr[mt][1] = *(const uint32_t*)&Ab[(rb + 8) * KP + kk + 2 * tig];
                afr[mt][2] = *(const uint32_t*)&Ab[(rb)     * KP + kk + 8 + 2 * tig];
                afr[mt][3] = *(const uint32_t*)&Ab[(rb + 8) * KP + kk + 8 + 2 * tig];
            }
            uint32_t bfr[NF][2];
            #pragma unroll
            for (int f = 0; f < NF; f++) {
                int nr = n_base + f * 8 + g;
                bfr[f][0] = *(const uint32_t*)&Bb[nr * KP + kk + 2 * tig];
                bfr[f][1] = *(const uint32_t*)&Bb[nr * KP + kk + 8 + 2 * tig];
            }
            #pragma unroll
            for (int mt = 0; mt < 2; mt++)
                #pragma unroll
                for (int f = 0; f < NF; f++)
                    mma_f16(acc[mt][f], afr[mt], bfr[f]);
        }
        __syncthreads();
        if (c + 2 < nch) load_chunk(c + 2, buf);
    }

    float* outf = (float*)out_v;
    __half* outh = (__half*)out_v;
    #pragma unroll
    for (int mt = 0; mt < 2; mt++) {
        int row = row0 + m_base + mt * 16 + g;
        #pragma unroll
        for (int f = 0; f < NF; f++) {
            int col = n_base + f * 8 + 2 * tig;
            if (col >= fout) continue;
            float bx = bias_s[col], by = bias_s[col + 1];
            float v0 = acc[mt][f][0] + bx, v1 = acc[mt][f][1] + by;
            float v2 = acc[mt][f][2] + bx, v3 = acc[mt][f][3] + by;
            if (do_relu) {
                v0 = fmaxf(v0, 0.f); v1 = fmaxf(v1, 0.f);
                v2 = fmaxf(v2, 0.f); v3 = fmaxf(v3, 0.f);
            }
            if (OUT_HALF) {
                if (row < n)
                    *(__half2*)(outh + (size_t)row * fout + col) = __floats2half2_rn(v0, v1);
                if (row + 8 < n)
                    *(__half2*)(outh + (size_t)(row + 8) * fout + col) = __floats2half2_rn(v2, v3);
            } else {
                if (row < n)
                    *(float2*)(outf + (size_t)row * fout + col) = make_float2(v0, v1);
                if (row + 8 < n)
                    *(float2*)(outf + (size_t)(row + 8) * fout + col) = make_float2(v2, v3);
            }
        }
    }
}

// ------------- fused combine-1 + pool-2 (all dims 128) -----------------------
__global__ void __launch_bounds__(256, 2) fused_mid_kernel(
    const __half* __restrict__ X0, const __half* __restrict__ X1,
    const __half* __restrict__ W0, const __half* __restrict__ W1,
    const __half* __restrict__ W2,
    const float* __restrict__ b0, const float* __restrict__ b1,
    const float* __restrict__ b2,
    __half* __restrict__ out_h, __half* __restrict__ out_m, int n)
{
    extern __shared__ __align__(16) __half smem_h[];
    __half* As = smem_h;                     // [2][128*KP]
    __half* Bs = smem_h + 2 * 128 * KP;      // [2][128*KP]
    float* bias_s  = (float*)(smem_h + 4 * 128 * KP);   // [128]
    float* bias2_s = bias_s + 128;                       // [128]

    const int tid   = threadIdx.x;
    const int lane  = tid & 31, wid = tid >> 5;
    const int g     = lane >> 2, tig = lane & 3;
    const int m_base = (wid & 3) * 32;
    const int n_base = (wid >> 2) * 64;
    const int row0  = blockIdx.x * 128;
    const uint32_t sbA = smem_to_u32(smem_h);
    const uint32_t sbB = sbA + 2 * 128 * KP * 2;

    if (tid < 128) {
        bias_s[tid]  = b0[tid] + b1[tid];
        bias2_s[tid] = b2[tid];
    }

    auto load_chunk = [&](int c, int buf) {
        const __half* X = (c < 2) ? X0 : X1;
        const __half* W = (c < 2) ? W0 : W1;
        const int kc = (c & 1) * 64;
        #pragma unroll
        for (int i = 0; i < 4; i++) {
            int lin = i * 256 + tid;
            int r = lin >> 3, s = lin & 7;
            int gr = row0 + r;
            int ok = (gr < n);
            const __half* src = X + (size_t)(ok ? gr : 0) * 128 + kc + s * 8;
            uint32_t sa = sbA + (uint32_t)(buf * 128 * KP + r * KP + s * 8) * 2;
            CPASYNC16(sa, src, ok ? 16 : 0);
        }
        #pragma unroll
        for (int i = 0; i < 4; i++) {
            int lin = i * 256 + tid;
            int r = lin >> 3, s = lin & 7;
            const __half* src = W + (size_t)r * 128 + kc + s * 8;
            uint32_t sa = sbB + (uint32_t)(buf * 128 * KP + r * KP + s * 8) * 2;
            CPASYNC16(sa, src, 16);
        }
        CPCOMMIT();
    };
    auto load_w2_chunk = [&](int idx) {
        const int kc = idx * 64;
        #pragma unroll
        for (int i = 0; i < 4; i++) {
            int lin = i * 256 + tid;
            int r = lin >> 3, s = lin & 7;
            const __half* src = W2 + (size_t)r * 128 + kc + s * 8;
            uint32_t sa = sbB + (uint32_t)(idx * 128 * KP + r * KP + s * 8) * 2;
            CPASYNC16(sa, src, 16);
        }
        CPCOMMIT();
    };

    float acc[2][8][4];
    auto zero_acc = [&]() {
        #pragma unroll
        for (int mt = 0; mt < 2; mt++)
            #pragma unroll
            for (int f = 0; f < 8; f++)
                #pragma unroll
                for (int j = 0; j < 4; j++) acc[mt][f][j] = 0.f;
    };
    auto compute_chunk = [&](const __half* Ab, const __half* Bb) {
        #pragma unroll
        for (int kk = 0; kk < 64; kk += 16) {
            uint32_t afr[2][4];
            #pragma unroll
            for (int mt = 0; mt < 2; mt++) {
                int rb = m_base + mt * 16 + g;
                afr[mt][0] = *(const uint32_t*)&Ab[(rb)     * KP + kk + 2 * tig];
                afr[mt][1] = *(const uint32_t*)&Ab[(rb + 8) * KP + kk + 2 * tig];
                afr[mt][2] = *(const uint32_t*)&Ab[(rb)     * KP + kk + 8 + 2 * tig];
                afr[mt][3] = *(const uint32_t*)&Ab[(rb + 8) * KP + kk + 8 + 2 * tig];
            }
            uint32_t bfr[8][2];
            #pragma unroll
            for (int f = 0; f < 8; f++) {
                int nr = n_base + f * 8 + g;
                bfr[f][0] = *(const uint32_t*)&Bb[nr * KP + kk + 2 * tig];
                bfr[f][1] = *(const uint32_t*)&Bb[nr * KP + kk + 8 + 2 * tig];
            }
            #pragma unroll
            for (int mt = 0; mt < 2; mt++)
                #pragma unroll
                for (int f = 0; f < 8; f++)
                    mma_f16(acc[mt][f], afr[mt], bfr[f]);
        }
    };

    zero_acc();
    load_chunk(0, 0);
    load_chunk(1, 1);

    #pragma unroll
    for (int c = 0; c < 4; c++) {
        CPWAIT(1);
        __syncthreads();
        const int buf = c & 1;
        compute_chunk(As + buf * 128 * KP, Bs + buf * 128 * KP);
        __syncthreads();
        if (c < 2) load_chunk(c + 2, buf);
        else       load_w2_chunk(c - 2);
    }

    #pragma unroll
    for (int mt = 0; mt < 2; mt++) {
        int lrow = m_base + mt * 16 + g;
        int row  = row0 + lrow;
        #pragma unroll
        for (int f = 0; f < 8; f++) {
            int col = n_base + f * 8 + 2 * tig;
            float bx = bias_s[col], by = bias_s[col + 1];
            float v0 = fmaxf(acc[mt][f][0] + bx, 0.f);
            float v1 = fmaxf(acc[mt][f][1] + by, 0.f);
            float v2 = fmaxf(acc[mt][f][2] + bx, 0.f);
            float v3 = fmaxf(acc[mt][f][3] + by, 0.f);
            __half2 h01 = __floats2half2_rn(v0, v1);
            __half2 h23 = __floats2half2_rn(v2, v3);
            if (row < n)
                *(__half2*)(out_h + (size_t)row * 128 + col) = h01;
            if (row + 8 < n)
                *(__half2*)(out_h + (size_t)(row + 8) * 128 + col) = h23;
            __half* dstA = As + (col >= 64 ? 1 : 0) * 128 * KP;
            int ck = col & 63;
            *(__half2*)&dstA[(lrow)     * KP + ck] = h01;
            *(__half2*)&dstA[(lrow + 8) * KP + ck] = h23;
        }
    }
    CPWAIT(0);
    __syncthreads();

    zero_acc();
    compute_chunk(As, Bs);
    compute_chunk(As + 128 * KP, Bs + 128 * KP);

    #pragma unroll
    for (int mt = 0; mt < 2; mt++) {
        int row = row0 + m_base + mt * 16 + g;
        #pragma unroll
        for (int f = 0; f < 8; f++) {
            int col = n_base + f * 8 + 2 * tig;
            float bx = bias2_s[col], by = bias2_s[col + 1];
            float v0 = fmaxf(acc[mt][f][0] + bx, 0.f);
            float v1 = fmaxf(acc[mt][f][1] + by, 0.f);
            float v2 = fmaxf(acc[mt][f][2] + bx, 0.f);
            float v3 = fmaxf(acc[mt][f][3] + by, 0.f);
            if (row < n)
                *(__half2*)(out_m + (size_t)row * 128 + col) = __floats2half2_rn(v0, v1);
            if (row + 8 < n)
                *(__half2*)(out_m + (size_t)(row + 8) * 128 + col) = __floats2half2_rn(v2, v3);
        }
    }
}

// ------------------------- fused prep: conv_x | conv_w | hist ------------------
#define CXB 12500   // conv_x blocks (NN*FDIM/4/256)
#define CWB 296     // conv_w blocks (75776/256)
#define HB  6250    // hist blocks (NE/256)
__global__ void __launch_bounds__(256) prep_kernel(
    const float4* __restrict__ in_feat, __half2* __restrict__ xh,
    const float* w1, const float* w2, const float* w3,
    const float* w4, const float* w5, const float* w6,
    __half* __restrict__ wh,
    const int* __restrict__ dst, int* __restrict__ deg)
{
    int b = blockIdx.x;
    if (b < CXB) {
        int i = b * 256 + threadIdx.x;
        float4 v = in_feat[i];
        xh[i * 2 + 0] = __floats2half2_rn(v.x, v.y);
        xh[i * 2 + 1] = __floats2half2_rn(v.z, v.w);
    } else if (b < CXB + CWB) {
        int i = (b - CXB) * 256 + threadIdx.x;
        const float* s; int off;
        if      (i < 16384) { s = w1; off = i; }
        else if (i < 32768) { s = w2; off = i - 16384; }
        else if (i < 49152) { s = w3; off = i - 32768; }
        else if (i < 65536) { s = w4; off = i - 49152; }
        else if (i < 70656) { s = w5; off = i - 65536; }
        else if (i < 75776) { s = w6; off = i - 70656; }
        else return;
        wh[i] = __float2half_rn(s[off]);
    } else {
        int e = (b - CXB - CWB) * 256 + threadIdx.x;
        if (e < NE) atomicAdd(&deg[dst[e]], 1);
    }
}

// ------------------------- CSR scan + scatter ----------------------------------
// scanA: per-1024-tile exclusive scan (tile-LOCAL, no global offset); tile sums
// to part[]. Rewrites off fully each launch -> replay-safe despite scatter's
// later mutation of off.
__global__ void __launch_bounds__(1024) scanA_kernel(
    const int* __restrict__ deg, int* __restrict__ off, int* __restrict__ part)
{
    __shared__ int wsum[32];
    const int tid = threadIdx.x, lane = tid & 31, w = tid >> 5;
    int idx = blockIdx.x * 1024 + tid;
    int v = (idx < NN) ? deg[idx] : 0;
    int incl = v;
    #pragma unroll
    for (int d = 1; d < 32; d <<= 1) {
        int t = __shfl_up_sync(~0u, incl, d);
        if (lane >= d) incl += t;
    }
    if (lane == 31) wsum[w] = incl;
    __syncthreads();
    if (w == 0) {
        int s = wsum[lane], si = s;
        #pragma unroll
        for (int d = 1; d < 32; d <<= 1) {
            int t = __shfl_up_sync(~0u, si, d);
            if (lane >= d) si += t;
        }
        wsum[lane] = si - s;
    }
    __syncthreads();
    int excl = incl - v + wsum[w];
    if (idx < NN) off[idx] = excl;
    if (tid == 1023) part[blockIdx.x] = excl + v;
}

// scanB: exclusive-scan the tile sums in place.
__global__ void __launch_bounds__(128) scanB_kernel(int* __restrict__ part, int ntiles)
{
    __shared__ int wsum[4];
    const int tid = threadIdx.x, lane = tid & 31, w = tid >> 5;
    int v = (tid < ntiles) ? part[tid] : 0;
    int incl = v;
    #pragma unroll
    for (int d = 1; d < 32; d <<= 1) {
        int t = __shfl_up_sync(~0u, incl, d);
        if (lane >= d) incl += t;
    }
    if (lane == 31) wsum[w] = incl;
    __syncthreads();
    int woff = 0;
    #pragma unroll
    for (int i = 0; i < 4; i++) if (i < w) woff += wsum[i];
    if (tid < ntiles) part[tid] = incl - v + woff;
}

// scatter: global pos = tile-local cursor (atomicAdd on off) + tile prefix.
// After this, off[i] = tile-local INCLUSIVE prefix.
__global__ void scatter_kernel(const int* __restrict__ src, const int* __restrict__ dst,
                               int* __restrict__ off, const int* __restrict__ part,
                               int* __restrict__ csr)
{
    int e = blockIdx.x * 256 + threadIdx.x;
    if (e < NE) {
        int d = dst[e];
        int p = atomicAdd(&off[d], 1) + __ldg(&part[d >> 10]);
        csr[p] = src[e];
    }
}

// ------------------------- segment-max via CSR ---------------------------------
// Warp per node; half-warps process 2 edges per step, each lane loads uint4
// (16 B -> 16 lanes cover a 256 B row). Post-ReLU values >= 0: 0-init is exact.
// Row bounds: [off[n-1]+part[(n-1)>>10], off[n]+part[n>>10])  (off = local incl.)
__global__ void __launch_bounds__(256) agg_kernel(
    const int* __restrict__ off, const int* __restrict__ part,
    const int* __restrict__ csr,
    const uint4* __restrict__ m4, __half2* __restrict__ agg2)
{
    int node = blockIdx.x * 8 + (threadIdx.x >> 5);
    if (node >= NN) return;
    int lane = threadIdx.x & 31;
    int sub  = lane >> 4;        // half-warp id (0/1)
    int cg   = lane & 15;        // uint4 index within the 16-uint4 row
    int st = node ? __ldg(&off[node - 1]) + __ldg(&part[(node - 1) >> 10]) : 0;
    int en = __ldg(&off[node]) + __ldg(&part[node >> 10]);

    uint4 mx = make_uint4(0u, 0u, 0u, 0u);
    int i = st;
    for (; i + 4 <= en; i += 4) {
        int s0 = __ldg(&csr[i + sub]);
        int s1 = __ldg(&csr[i + 2 + sub]);
        uint4 v0 = __ldg(&m4[(size_t)s0 * 16 + cg]);
        uint4 v1 = __ldg(&m4[(size_t)s1 * 16 + cg]);
        mx.x = hmax2u(mx.x, hmax2u(v0.x, v1.x));
        mx.y = hmax2u(mx.y, hmax2u(v0.y, v1.y));
        mx.z = hmax2u(mx.z, hmax2u(v0.z, v1.z));
        mx.w = hmax2u(mx.w, hmax2u(v0.w, v1.w));
    }
    for (; i < en; i += 2) {
        int j = i + sub;
        int s = __ldg(&csr[j < en ? j : i]);
        uint4 v = __ldg(&m4[(size_t)s * 16 + cg]);
        mx.x = hmax2u(mx.x, v.x);
        mx.y = hmax2u(mx.y, v.y);
        mx.z = hmax2u(mx.z, v.z);
        mx.w = hmax2u(mx.w, v.w);
    }
    // merge the two half-warps
    mx.x = hmax2u(mx.x, __shfl_xor_sync(~0u, mx.x, 16));
    mx.y = hmax2u(mx.y, __shfl_xor_sync(~0u, mx.y, 16));
    mx.z = hmax2u(mx.z, __shfl_xor_sync(~0u, mx.z, 16));
    mx.w = hmax2u(mx.w, __shfl_xor_sync(~0u, mx.w, 16));
    if (sub == 0)
        ((uint4*)(agg2 + (size_t)node * 64))[cg] = mx;
}

// ===============================================================================
extern "C" void kernel_launch(void* const* d_in, const int* in_sizes, int n_in,
                              void* d_out, int out_size)
{
    const float* in_feat  = (const float*)d_in[0];
    const int*   src      = (const int*)  d_in[1];
    const int*   dst      = (const int*)  d_in[2];
    const float* pool_w1  = (const float*)d_in[3];
    const float* pool_b1  = (const float*)d_in[4];
    const float* self_w1  = (const float*)d_in[5];
    const float* self_b1  = (const float*)d_in[6];
    const float* neigh_w1 = (const float*)d_in[7];
    const float* neigh_b1 = (const float*)d_in[8];
    const float* pool_w2  = (const float*)d_in[9];
    const float* pool_b2  = (const float*)d_in[10];
    const float* self_w2  = (const float*)d_in[11];
    const float* self_b2  = (const float*)d_in[12];
    const float* neigh_w2 = (const float*)d_in[13];
    const float* neigh_b2 = (const float*)d_in[14];

    __half *mh, *aggh, *hh, *xh, *wh;
    int *deg, *off, *csr, *part;
    cudaGetSymbolAddress((void**)&mh,   g_mh);
    cudaGetSymbolAddress((void**)&aggh, g_aggh);
    cudaGetSymbolAddress((void**)&hh,   g_hh);
    cudaGetSymbolAddress((void**)&xh,   g_xh);
    cudaGetSymbolAddress((void**)&wh,   g_wh);
    cudaGetSymbolAddress((void**)&deg,  g_deg);
    cudaGetSymbolAddress((void**)&off,  g_off);
    cudaGetSymbolAddress((void**)&csr,  g_csr);
    cudaGetSymbolAddress((void**)&part, g_part);

    const int ggrid  = (NN + 127) / 128;     // 782
    const int ngrid  = (NN + 7) / 8;
    const int ntiles = (NN + 1023) / 1024;   // 98
    const int SMEM_128  = (2 * 128 * KP + 2 * 128 * KP) * 2 + 128 * 4;   // 74240 B
    const int SMEM_48   = (2 * 128 * KP + 2 * 48 * KP) * 2 + 48 * 4;     // 50880 B
    const int SMEM_FUSE = 4 * 128 * KP * 2 + 256 * 4;                    // 74752 B

    cudaFuncSetAttribute(mma_gemm_kernel<128, false, true>,
                         cudaFuncAttributeMaxDynamicSharedMemorySize, SMEM_128);
    cudaFuncSetAttribute(mma_gemm_kernel<48, true, false>,
                         cudaFuncAttributeMaxDynamicSharedMemorySize, SMEM_48);
    cudaFuncSetAttribute(fused_mid_kernel,
                         cudaFuncAttributeMaxDynamicSharedMemorySize, SMEM_FUSE);

    // ---- prep (fused conv_x|conv_w|hist) + CSR, single stream ----
    cudaMemsetAsync(deg, 0, NN * sizeof(int));
    prep_kernel<<<CXB + CWB + HB, 256>>>((const float4*)in_feat, (__half2*)xh,
                                         pool_w1, self_w1, neigh_w1,
                                         pool_w2, self_w2, neigh_w2, wh, dst, deg);
    scanA_kernel<<<ntiles, 1024>>>(deg, off, part);
    scanB_kernel<<<1, 128>>>(part, ntiles);
    scatter_kernel<<<(NE + 255) / 256, 256>>>(src, dst, off, part, csr);

    // ---- layer 1 pool ----
    mma_gemm_kernel<128, false, true><<<ggrid, 256, SMEM_128>>>(
        xh, nullptr, wh + WR_PW1, nullptr, pool_b1, nullptr, mh, NN, FDIM, 1);
    agg_kernel<<<ngrid, 256>>>(off, part, csr, (const uint4*)mh, (__half2*)aggh);

    // ---- fused: combine-1 + pool-2 ----
    fused_mid_kernel<<<ggrid, 256, SMEM_FUSE>>>(
        xh, aggh, wh + WR_SW1, wh + WR_NW1, wh + WR_PW2,
        self_b1, neigh_b1, pool_b2, hh, mh, NN);
    agg_kernel<<<ngrid, 256>>>(off, part, csr, (const uint4*)mh, (__half2*)aggh);

    // ---- layer-2 combine (BN=48 covers fout=40) ----
    mma_gemm_kernel<48, true, false><<<ggrid, 256, SMEM_48>>>(
        hh, aggh, wh + WR_SW2, wh + WR_NW2, self_b2, neigh_b2, (float*)d_out, NN, NCLS, 0);
}

// round 14
// speedup vs baseline: 1.0308x; 1.0308x over previous
#include <cuda_runtime.h>
#include <cuda_fp16.h>
#include <cstdint>

#define NN 100000
#define NE 1600000
#define FDIM 128
#define NCLS 40

// ------------------------- device scratch (no allocs) -----------------------
__device__ __align__(16) __half g_mh[(size_t)NN * FDIM];   // pool messages (fp16)
__device__ __align__(16) __half g_aggh[(size_t)NN * FDIM]; // segment-max agg (fp16)
__device__ __align__(16) __half g_hh[(size_t)NN * FDIM];   // layer-1 hidden (fp16)
__device__ __align__(16) __half g_xh[(size_t)NN * FDIM];   // fp16 in_feat
__device__ __align__(16) __half g_wh[75776];               // fp16 weights (6 matrices)
__device__ int   g_deg[NN];      // zero at load; scanA re-zeroes each launch
__device__ int   g_off[NN + 1];  // tile-local excl after scanA; local incl after scatter
__device__ int   g_csr[NE];
__device__ int   g_part[128];    // tile partials; exclusive-scanned by scanA's last block
__device__ int   g_sync;         // scanA last-block counter (self-resetting)

// weight offsets inside g_wh
#define WR_PW1 0
#define WR_SW1 16384
#define WR_NW1 32768
#define WR_PW2 49152
#define WR_SW2 65536
#define WR_NW2 70656

// ------------------------- PTX helpers --------------------------------------
__device__ __forceinline__ uint32_t smem_to_u32(const void* p) {
    uint32_t a;
    asm("{ .reg .u64 t; cvta.to.shared.u64 t, %1; cvt.u32.u64 %0, t; }"
        : "=r"(a) : "l"(p));
    return a;
}
#define CPASYNC16(sa, ga, sz) \
    asm volatile("cp.async.cg.shared.global [%0], [%1], 16, %2;" \
                 :: "r"(sa), "l"(ga), "r"(sz))
#define CPCOMMIT() asm volatile("cp.async.commit_group;" ::: "memory")
#define CPWAIT(N)  asm volatile("cp.async.wait_group %0;" :: "n"(N) : "memory")

// m16n8k16 fp16 HMMA, f32 accum. Base PTX (sm_80+): compiles at compute_103.
__device__ __forceinline__ void mma_f16(float* d, const uint32_t* a, const uint32_t* b)
{
    asm volatile(
        "mma.sync.aligned.m16n8k16.row.col.f32.f16.f16.f32 "
        "{%0,%1,%2,%3}, {%4,%5,%6,%7}, {%8,%9}, {%0,%1,%2,%3};"
        : "+f"(d[0]), "+f"(d[1]), "+f"(d[2]), "+f"(d[3])
        : "r"(a[0]), "r"(a[1]), "r"(a[2]), "r"(a[3]),
          "r"(b[0]), "r"(b[1]));
}

__device__ __forceinline__ uint32_t hmax2u(uint32_t a, uint32_t b)
{
    __half2 r = __hmax2(*(__half2*)&a, *(__half2*)&b);
    return *(uint32_t*)&r;
}

#define KP 72   // padded smem k stride (halves)

// ------------------------- fp16 warp-MMA GEMM (generic) ----------------------
template<int BN, bool DUAL, bool OUT_HALF>
__global__ void __launch_bounds__(256, 2) mma_gemm_kernel(
    const __half* __restrict__ X0, const __half* __restrict__ X1,
    const __half* __restrict__ W0, const __half* __restrict__ W1,
    const float* __restrict__ b0, const float* __restrict__ b1,
    void* __restrict__ out_v, int n, int fout, int do_relu)
{
    constexpr int NF = BN / 16;
    extern __shared__ __align__(16) __half smem_h[];
    __half* As = smem_h;                     // [2][128*KP]
    __half* Bs = smem_h + 2 * 128 * KP;      // [2][BN*KP]
    float* bias_s = (float*)(smem_h + 2 * 128 * KP + 2 * BN * KP);

    const int tid   = threadIdx.x;
    const int lane  = tid & 31, wid = tid >> 5;
    const int g     = lane >> 2, tig = lane & 3;
    const int m_base = (wid & 3) * 32;
    const int n_base = (wid >> 2) * (BN / 2);
    const int row0  = blockIdx.x * 128;
    const uint32_t sbA = smem_to_u32(smem_h);
    const uint32_t sbB = sbA + 2 * 128 * KP * 2;

    if (tid < BN) {
        float bv = 0.f;
        if (tid < fout) { bv = b0[tid]; if (b1 != nullptr) bv += b1[tid]; }
        bias_s[tid] = bv;
    }

    auto load_chunk = [&](int c, int buf) {
        const __half* X = (c < 2) ? X0 : X1;
        const __half* W = (c < 2) ? W0 : W1;
        const int kc = (c & 1) * 64;
        #pragma unroll
        for (int i = 0; i < 4; i++) {
            int lin = i * 256 + tid;
            int r = lin >> 3, s = lin & 7;
            int gr = row0 + r;
            int ok = (gr < n);
            const __half* src = X + (size_t)(ok ? gr : 0) * 128 + kc + s * 8;
            uint32_t sa = sbA + (uint32_t)(buf * 128 * KP + r * KP + s * 8) * 2;
            CPASYNC16(sa, src, ok ? 16 : 0);
        }
        #pragma unroll
        for (int i = 0; i < (BN * 8 + 255) / 256; i++) {
            int lin = i * 256 + tid;
            if (lin < BN * 8) {
                int r = lin >> 3, s = lin & 7;
                int ok = (r < fout);
                const __half* src = W + (size_t)(ok ? r : 0) * 128 + kc + s * 8;
                uint32_t sa = sbB + (uint32_t)(buf * BN * KP + r * KP + s * 8) * 2;
                CPASYNC16(sa, src, ok ? 16 : 0);
            }
        }
        CPCOMMIT();
    };

    float acc[2][NF][4];
    #pragma unroll
    for (int mt = 0; mt < 2; mt++)
        #pragma unroll
        for (int f = 0; f < NF; f++)
            #pragma unroll
            for (int j = 0; j < 4; j++) acc[mt][f][j] = 0.f;

    const int nch = DUAL ? 4 : 2;
    load_chunk(0, 0);
    load_chunk(1, 1);

    for (int c = 0; c < nch; c++) {
        if (c + 1 < nch) { CPWAIT(1); } else { CPWAIT(0); }
        __syncthreads();
        const int buf = c & 1;
        const __half* Ab = As + buf * 128 * KP;
        const __half* Bb = Bs + buf * BN * KP;
        #pragma unroll
        for (int kk = 0; kk < 64; kk += 16) {
            uint32_t afr[2][4];
            #pragma unroll
            for (int mt = 0; mt < 2; mt++) {
                int rb = m_base + mt * 16 + g;
                afr[mt][0] = *(const uint32_t*)&Ab[(rb)     * KP + kk + 2 * tig];
                afr[mt][1] = *(const uint32_t*)&Ab[(rb + 8) * KP + kk + 2 * tig];
                afr[mt][2] = *(const uint32_t*)&Ab[(rb)     * KP + kk + 8 + 2 * tig];
                afr[mt][3] = *(const uint32_t*)&Ab[(rb + 8) * KP + kk + 8 + 2 * tig];
            }
            uint32_t bfr[NF][2];
            #pragma unroll
            for (int f = 0; f < NF; f++) {
                int nr = n_base + f * 8 + g;
                bfr[f][0] = *(const uint32_t*)&Bb[nr * KP + kk + 2 * tig];
                bfr[f][1] = *(const uint32_t*)&Bb[nr * KP + kk + 8 + 2 * tig];
            }
            #pragma unroll
            for (int mt = 0; mt < 2; mt++)
                #pragma unroll
                for (int f = 0; f < NF; f++)
                    mma_f16(acc[mt][f], afr[mt], bfr[f]);
        }
        __syncthreads();
        if (c + 2 < nch) load_chunk(c + 2, buf);
    }

    float* outf = (float*)out_v;
    __half* outh = (__half*)out_v;
    #pragma unroll
    for (int mt = 0; mt < 2; mt++) {
        int row = row0 + m_base + mt * 16 + g;
        #pragma unroll
        for (int f = 0; f < NF; f++) {
            int col = n_base + f * 8 + 2 * tig;
            if (col >= fout) continue;
            float bx = bias_s[col], by = bias_s[col + 1];
            float v0 = acc[mt][f][0] + bx, v1 = acc[mt][f][1] + by;
            float v2 = acc[mt][f][2] + bx, v3 = acc[mt][f][3] + by;
            if (do_relu) {
                v0 = fmaxf(v0, 0.f); v1 = fmaxf(v1, 0.f);
                v2 = fmaxf(v2, 0.f); v3 = fmaxf(v3, 0.f);
            }
            if (OUT_HALF) {
                if (row < n)
                    *(__half2*)(outh + (size_t)row * fout + col) = __floats2half2_rn(v0, v1);
                if (row + 8 < n)
                    *(__half2*)(outh + (size_t)(row + 8) * fout + col) = __floats2half2_rn(v2, v3);
            } else {
                if (row < n)
                    *(float2*)(outf + (size_t)row * fout + col) = make_float2(v0, v1);
                if (row + 8 < n)
                    *(float2*)(outf + (size_t)(row + 8) * fout + col) = make_float2(v2, v3);
            }
        }
    }
}

// ------------- fused combine-1 + pool-2 (all dims 128) -----------------------
__global__ void __launch_bounds__(256, 2) fused_mid_kernel(
    const __half* __restrict__ X0, const __half* __restrict__ X1,
    const __half* __restrict__ W0, const __half* __restrict__ W1,
    const __half* __restrict__ W2,
    const float* __restrict__ b0, const float* __restrict__ b1,
    const float* __restrict__ b2,
    __half* __restrict__ out_h, __half* __restrict__ out_m, int n)
{
    extern __shared__ __align__(16) __half smem_h[];
    __half* As = smem_h;                     // [2][128*KP]
    __half* Bs = smem_h + 2 * 128 * KP;      // [2][128*KP]
    float* bias_s  = (float*)(smem_h + 4 * 128 * KP);   // [128]
    float* bias2_s = bias_s + 128;                       // [128]

    const int tid   = threadIdx.x;
    const int lane  = tid & 31, wid = tid >> 5;
    const int g     = lane >> 2, tig = lane & 3;
    const int m_base = (wid & 3) * 32;
    const int n_base = (wid >> 2) * 64;
    const int row0  = blockIdx.x * 128;
    const uint32_t sbA = smem_to_u32(smem_h);
    const uint32_t sbB = sbA + 2 * 128 * KP * 2;

    if (tid < 128) {
        bias_s[tid]  = b0[tid] + b1[tid];
        bias2_s[tid] = b2[tid];
    }

    auto load_chunk = [&](int c, int buf) {
        const __half* X = (c < 2) ? X0 : X1;
        const __half* W = (c < 2) ? W0 : W1;
        const int kc = (c & 1) * 64;
        #pragma unroll
        for (int i = 0; i < 4; i++) {
            int lin = i * 256 + tid;
            int r = lin >> 3, s = lin & 7;
            int gr = row0 + r;
            int ok = (gr < n);
            const __half* src = X + (size_t)(ok ? gr : 0) * 128 + kc + s * 8;
            uint32_t sa = sbA + (uint32_t)(buf * 128 * KP + r * KP + s * 8) * 2;
            CPASYNC16(sa, src, ok ? 16 : 0);
        }
        #pragma unroll
        for (int i = 0; i < 4; i++) {
            int lin = i * 256 + tid;
            int r = lin >> 3, s = lin & 7;
            const __half* src = W + (size_t)r * 128 + kc + s * 8;
            uint32_t sa = sbB + (uint32_t)(buf * 128 * KP + r * KP + s * 8) * 2;
            CPASYNC16(sa, src, 16);
        }
        CPCOMMIT();
    };
    auto load_w2_chunk = [&](int idx) {
        const int kc = idx * 64;
        #pragma unroll
        for (int i = 0; i < 4; i++) {
            int lin = i * 256 + tid;
            int r = lin >> 3, s = lin & 7;
            const __half* src = W2 + (size_t)r * 128 + kc + s * 8;
            uint32_t sa = sbB + (uint32_t)(idx * 128 * KP + r * KP + s * 8) * 2;
            CPASYNC16(sa, src, 16);
        }
        CPCOMMIT();
    };

    float acc[2][8][4];
    auto zero_acc = [&]() {
        #pragma unroll
        for (int mt = 0; mt < 2; mt++)
            #pragma unroll
            for (int f = 0; f < 8; f++)
                #pragma unroll
                for (int j = 0; j < 4; j++) acc[mt][f][j] = 0.f;
    };
    auto compute_chunk = [&](const __half* Ab, const __half* Bb) {
        #pragma unroll
        for (int kk = 0; kk < 64; kk += 16) {
            uint32_t afr[2][4];
            #pragma unroll
            for (int mt = 0; mt < 2; mt++) {
                int rb = m_base + mt * 16 + g;
                afr[mt][0] = *(const uint32_t*)&Ab[(rb)     * KP + kk + 2 * tig];
                afr[mt][1] = *(const uint32_t*)&Ab[(rb + 8) * KP + kk + 2 * tig];
                afr[mt][2] = *(const uint32_t*)&Ab[(rb)     * KP + kk + 8 + 2 * tig];
                afr[mt][3] = *(const uint32_t*)&Ab[(rb + 8) * KP + kk + 8 + 2 * tig];
            }
            uint32_t bfr[8][2];
            #pragma unroll
            for (int f = 0; f < 8; f++) {
                int nr = n_base + f * 8 + g;
                bfr[f][0] = *(const uint32_t*)&Bb[nr * KP + kk + 2 * tig];
                bfr[f][1] = *(const uint32_t*)&Bb[nr * KP + kk + 8 + 2 * tig];
            }
            #pragma unroll
            for (int mt = 0; mt < 2; mt++)
                #pragma unroll
                for (int f = 0; f < 8; f++)
                    mma_f16(acc[mt][f], afr[mt], bfr[f]);
        }
    };

    zero_acc();
    load_chunk(0, 0);
    load_chunk(1, 1);

    #pragma unroll
    for (int c = 0; c < 4; c++) {
        CPWAIT(1);
        __syncthreads();
        const int buf = c & 1;
        compute_chunk(As + buf * 128 * KP, Bs + buf * 128 * KP);
        __syncthreads();
        if (c < 2) load_chunk(c + 2, buf);
        else       load_w2_chunk(c - 2);
    }

    #pragma unroll
    for (int mt = 0; mt < 2; mt++) {
        int lrow = m_base + mt * 16 + g;
        int row  = row0 + lrow;
        #pragma unroll
        for (int f = 0; f < 8; f++) {
            int col = n_base + f * 8 + 2 * tig;
            float bx = bias_s[col], by = bias_s[col + 1];
            float v0 = fmaxf(acc[mt][f][0] + bx, 0.f);
            float v1 = fmaxf(acc[mt][f][1] + by, 0.f);
            float v2 = fmaxf(acc[mt][f][2] + bx, 0.f);
            float v3 = fmaxf(acc[mt][f][3] + by, 0.f);
            __half2 h01 = __floats2half2_rn(v0, v1);
            __half2 h23 = __floats2half2_rn(v2, v3);
            if (row < n)
                *(__half2*)(out_h + (size_t)row * 128 + col) = h01;
            if (row + 8 < n)
                *(__half2*)(out_h + (size_t)(row + 8) * 128 + col) = h23;
            __half* dstA = As + (col >= 64 ? 1 : 0) * 128 * KP;
            int ck = col & 63;
            *(__half2*)&dstA[(lrow)     * KP + ck] = h01;
            *(__half2*)&dstA[(lrow + 8) * KP + ck] = h23;
        }
    }
    CPWAIT(0);
    __syncthreads();

    zero_acc();
    compute_chunk(As, Bs);
    compute_chunk(As + 128 * KP, Bs + 128 * KP);

    #pragma unroll
    for (int mt = 0; mt < 2; mt++) {
        int row = row0 + m_base + mt * 16 + g;
        #pragma unroll
        for (int f = 0; f < 8; f++) {
            int col = n_base + f * 8 + 2 * tig;
            float bx = bias2_s[col], by = bias2_s[col + 1];
            float v0 = fmaxf(acc[mt][f][0] + bx, 0.f);
            float v1 = fmaxf(acc[mt][f][1] + by, 0.f);
            float v2 = fmaxf(acc[mt][f][2] + bx, 0.f);
            float v3 = fmaxf(acc[mt][f][3] + by, 0.f);
            if (row < n)
                *(__half2*)(out_m + (size_t)row * 128 + col) = __floats2half2_rn(v0, v1);
            if (row + 8 < n)
                *(__half2*)(out_m + (size_t)(row + 8) * 128 + col) = __floats2half2_rn(v2, v3);
        }
    }
}

// ------------------------- fused prep: conv_x | conv_w | hist ------------------
#define CXB 12500   // conv_x blocks (NN*FDIM/4/256)
#define CWB 296     // conv_w blocks (75776/256)
#define HB  6250    // hist blocks (NE/256)
__global__ void __launch_bounds__(256) prep_kernel(
    const float4* __restrict__ in_feat, __half2* __restrict__ xh,
    const float* w1, const float* w2, const float* w3,
    const float* w4, const float* w5, const float* w6,
    __half* __restrict__ wh,
    const int* __restrict__ dst, int* __restrict__ deg)
{
    int b = blockIdx.x;
    if (b < CXB) {
        int i = b * 256 + threadIdx.x;
        float4 v = in_feat[i];
        xh[i * 2 + 0] = __floats2half2_rn(v.x, v.y);
        xh[i * 2 + 1] = __floats2half2_rn(v.z, v.w);
    } else if (b < CXB + CWB) {
        int i = (b - CXB) * 256 + threadIdx.x;
        const float* s; int off;
        if      (i < 16384) { s = w1; off = i; }
        else if (i < 32768) { s = w2; off = i - 16384; }
        else if (i < 49152) { s = w3; off = i - 32768; }
        else if (i < 65536) { s = w4; off = i - 49152; }
        else if (i < 70656) { s = w5; off = i - 65536; }
        else if (i < 75776) { s = w6; off = i - 70656; }
        else return;
        wh[i] = __float2half_rn(s[off]);
    } else {
        int e = (b - CXB - CWB) * 256 + threadIdx.x;
        if (e < NE) atomicAdd(&deg[dst[e]], 1);
    }
}

// ------------------------- CSR scan (A+B fused) + scatter ----------------------
// scanA: per-1024-tile exclusive scan (tile-LOCAL); zeroes deg for next launch;
// writes tile sum to part[]. The LAST block to finish (threadfence+atomic
// counter, self-resetting) exclusive-scans part[] in place (4x32 lanes covers
// ntiles <= 128) -> replay-safe, no separate scanB launch, no memset.
__global__ void __launch_bounds__(1024) scanA_kernel(
    int* __restrict__ deg, int* __restrict__ off, int* __restrict__ part,
    int* __restrict__ sync, int ntiles)
{
    __shared__ int wsum[32];
    __shared__ int last_s;
    const int tid = threadIdx.x, lane = tid & 31, w = tid >> 5;
    int idx = blockIdx.x * 1024 + tid;
    int v = 0;
    if (idx < NN) { v = deg[idx]; deg[idx] = 0; }      // self-clean for next launch
    int incl = v;
    #pragma unroll
    for (int d = 1; d < 32; d <<= 1) {
        int t = __shfl_up_sync(~0u, incl, d);
        if (lane >= d) incl += t;
    }
    if (lane == 31) wsum[w] = incl;
    __syncthreads();
    if (w == 0) {
        int s = wsum[lane], si = s;
        #pragma unroll
        for (int d = 1; d < 32; d <<= 1) {
            int t = __shfl_up_sync(~0u, si, d);
            if (lane >= d) si += t;
        }
        wsum[lane] = si - s;
    }
    __syncthreads();
    int excl = incl - v + wsum[w];
    if (idx < NN) off[idx] = excl;
    if (tid == 1023) {
        part[blockIdx.x] = excl + v;
        __threadfence();
        int done = atomicAdd(sync, 1);
        last_s = (done == ntiles - 1) ? 1 : 0;
    }
    __syncthreads();
    if (last_s) {
        // last block: exclusive-scan part[0..ntiles) with warp 0, 4x32 lanes
        if (w == 0) {
            int pv0 = (lane < ntiles)      ? part[lane]      : 0;
            int pv1 = (lane + 32 < ntiles) ? part[lane + 32] : 0;
            int pv2 = (lane + 64 < ntiles) ? part[lane + 64] : 0;
            int pv3 = (lane + 96 < ntiles) ? part[lane + 96] : 0;
            int i0 = pv0, i1 = pv1, i2 = pv2, i3 = pv3;
            #pragma unroll
            for (int d = 1; d < 32; d <<= 1) {
                int t0 = __shfl_up_sync(~0u, i0, d);
                int t1 = __shfl_up_sync(~0u, i1, d);
                int t2 = __shfl_up_sync(~0u, i2, d);
                int t3 = __shfl_up_sync(~0u, i3, d);
                if (lane >= d) { i0 += t0; i1 += t1; i2 += t2; i3 += t3; }
            }
            int s0 = __shfl_sync(~0u, i0, 31);
            int s1 = __shfl_sync(~0u, i1, 31);
            int s2 = __shfl_sync(~0u, i2, 31);
            if (lane < ntiles)      part[lane]      = i0 - pv0;
            if (lane + 32 < ntiles) part[lane + 32] = i1 - pv1 + s0;
            if (lane + 64 < ntiles) part[lane + 64] = i2 - pv2 + s0 + s1;
            if (lane + 96 < ntiles) part[lane + 96] = i3 - pv3 + s0 + s1 + s2;
            if (lane == 0) *sync = 0;                  // reset for next launch
        }
    }
}

// scatter: global pos = tile-local cursor (atomicAdd on off) + tile prefix.
// 2 edges per thread via int2 loads. After this, off[i] = tile-local INCLUSIVE.
__global__ void scatter_kernel(const int2* __restrict__ src2, const int2* __restrict__ dst2,
                               int* __restrict__ off, const int* __restrict__ part,
                               int* __restrict__ csr)
{
    int e2 = blockIdx.x * 256 + threadIdx.x;
    if (e2 < NE / 2) {
        int2 d = __ldg(&dst2[e2]);
        int2 s = __ldg(&src2[e2]);
        int p0 = atomicAdd(&off[d.x], 1) + __ldg(&part[d.x >> 10]);
        csr[p0] = s.x;
        int p1 = atomicAdd(&off[d.y], 1) + __ldg(&part[d.y >> 10]);
        csr[p1] = s.y;
    }
}

// ------------------------- segment-max via CSR ---------------------------------
// Warp per node; half-warps process edges in parallel, each lane loads uint4
// (16 lanes cover a 256 B row). 8-edge main loop -> 4 rows in flight per
// half-warp. Post-ReLU values >= 0: 0-init is exact.
__global__ void __launch_bounds__(256) agg_kernel(
    const int* __restrict__ off, const int* __restrict__ part,
    const int* __restrict__ csr,
    const uint4* __restrict__ m4, __half2* __restrict__ agg2)
{
    int node = blockIdx.x * 8 + (threadIdx.x >> 5);
    if (node >= NN) return;
    int lane = threadIdx.x & 31;
    int sub  = lane >> 4;
    int cg   = lane & 15;
    int st = node ? __ldg(&off[node - 1]) + __ldg(&part[(node - 1) >> 10]) : 0;
    int en = __ldg(&off[node]) + __ldg(&part[node >> 10]);

    uint4 mx = make_uint4(0u, 0u, 0u, 0u);
    int i = st;
    for (; i + 8 <= en; i += 8) {
        int s0 = __ldg(&csr[i + sub]);
        int s1 = __ldg(&csr[i + 2 + sub]);
        int s2 = __ldg(&csr[i + 4 + sub]);
        int s3 = __ldg(&csr[i + 6 + sub]);
        uint4 v0 = __ldg(&m4[(size_t)s0 * 16 + cg]);
        uint4 v1 = __ldg(&m4[(size_t)s1 * 16 + cg]);
        uint4 v2 = __ldg(&m4[(size_t)s2 * 16 + cg]);
        uint4 v3 = __ldg(&m4[(size_t)s3 * 16 + cg]);
        mx.x = hmax2u(mx.x, hmax2u(hmax2u(v0.x, v1.x), hmax2u(v2.x, v3.x)));
        mx.y = hmax2u(mx.y, hmax2u(hmax2u(v0.y, v1.y), hmax2u(v2.y, v3.y)));
        mx.z = hmax2u(mx.z, hmax2u(hmax2u(v0.z, v1.z), hmax2u(v2.z, v3.z)));
        mx.w = hmax2u(mx.w, hmax2u(hmax2u(v0.w, v1.w), hmax2u(v2.w, v3.w)));
    }
    for (; i < en; i += 2) {
        int j = i + sub;
        int s = __ldg(&csr[j < en ? j : i]);
        uint4 v = __ldg(&m4[(size_t)s * 16 + cg]);
        mx.x = hmax2u(mx.x, v.x);
        mx.y = hmax2u(mx.y, v.y);
        mx.z = hmax2u(mx.z, v.z);
        mx.w = hmax2u(mx.w, v.w);
    }
    mx.x = hmax2u(mx.x, __shfl_xor_sync(~0u, mx.x, 16));
    mx.y = hmax2u(mx.y, __shfl_xor_sync(~0u, mx.y, 16));
    mx.z = hmax2u(mx.z, __shfl_xor_sync(~0u, mx.z, 16));
    mx.w = hmax2u(mx.w, __shfl_xor_sync(~0u, mx.w, 16));
    if (sub == 0)
        ((uint4*)(agg2 + (size_t)node * 64))[cg] = mx;
}

// ===============================================================================
extern "C" void kernel_launch(void* const* d_in, const int* in_sizes, int n_in,
                              void* d_out, int out_size)
{
    const float* in_feat  = (const float*)d_in[0];
    const int*   src      = (const int*)  d_in[1];
    const int*   dst      = (const int*)  d_in[2];
    const float* pool_w1  = (const float*)d_in[3];
    const float* pool_b1  = (const float*)d_in[4];
    const float* self_w1  = (const float*)d_in[5];
    const float* self_b1  = (const float*)d_in[6];
    const float* neigh_w1 = (const float*)d_in[7];
    const float* neigh_b1 = (const float*)d_in[8];
    const float* pool_w2  = (const float*)d_in[9];
    const float* pool_b2  = (const float*)d_in[10];
    const float* self_w2  = (const float*)d_in[11];
    const float* self_b2  = (const float*)d_in[12];
    const float* neigh_w2 = (const float*)d_in[13];
    const float* neigh_b2 = (const float*)d_in[14];

    __half *mh, *aggh, *hh, *xh, *wh;
    int *deg, *off, *csr, *part, *sync;
    cudaGetSymbolAddress((void**)&mh,   g_mh);
    cudaGetSymbolAddress((void**)&aggh, g_aggh);
    cudaGetSymbolAddress((void**)&hh,   g_hh);
    cudaGetSymbolAddress((void**)&xh,   g_xh);
    cudaGetSymbolAddress((void**)&wh,   g_wh);
    cudaGetSymbolAddress((void**)&deg,  g_deg);
    cudaGetSymbolAddress((void**)&off,  g_off);
    cudaGetSymbolAddress((void**)&csr,  g_csr);
    cudaGetSymbolAddress((void**)&part, g_part);
    cudaGetSymbolAddress((void**)&sync, g_sync);

    const int ggrid  = (NN + 127) / 128;     // 782
    const int ngrid  = (NN + 7) / 8;
    const int ntiles = (NN + 1023) / 1024;   // 98
    const int SMEM_128  = (2 * 128 * KP + 2 * 128 * KP) * 2 + 128 * 4;   // 74240 B
    const int SMEM_48   = (2 * 128 * KP + 2 * 48 * KP) * 2 + 48 * 4;     // 50880 B
    const int SMEM_FUSE = 4 * 128 * KP * 2 + 256 * 4;                    // 74752 B

    cudaFuncSetAttribute(mma_gemm_kernel<128, false, true>,
                         cudaFuncAttributeMaxDynamicSharedMemorySize, SMEM_128);
    cudaFuncSetAttribute(mma_gemm_kernel<48, true, false>,
                         cudaFuncAttributeMaxDynamicSharedMemorySize, SMEM_48);
    cudaFuncSetAttribute(fused_mid_kernel,
                         cudaFuncAttributeMaxDynamicSharedMemorySize, SMEM_FUSE);

    // ---- prep (fused conv_x|conv_w|hist) + CSR (scanA+B fused), no memset ----
    prep_kernel<<<CXB + CWB + HB, 256>>>((const float4*)in_feat, (__half2*)xh,
                                         pool_w1, self_w1, neigh_w1,
                                         pool_w2, self_w2, neigh_w2, wh, dst, deg);
    scanA_kernel<<<ntiles, 1024>>>(deg, off, part, sync, ntiles);
    scatter_kernel<<<(NE / 2 + 255) / 256, 256>>>((const int2*)src, (const int2*)dst,
                                                  off, part, csr);

    // ---- layer 1 pool ----
    mma_gemm_kernel<128, false, true><<<ggrid, 256, SMEM_128>>>(
        xh, nullptr, wh + WR_PW1, nullptr, pool_b1, nullptr, mh, NN, FDIM, 1);
    agg_kernel<<<ngrid, 256>>>(off, part, csr, (const uint4*)mh, (__half2*)aggh);

    // ---- fused: combine-1 + pool-2 ----
    fused_mid_kernel<<<ggrid, 256, SMEM_FUSE>>>(
        xh, aggh, wh + WR_SW1, wh + WR_NW1, wh + WR_PW2,
        self_b1, neigh_b1, pool_b2, hh, mh, NN);
    agg_kernel<<<ngrid, 256>>>(off, part, csr, (const uint4*)mh, (__half2*)aggh);

    // ---- layer-2 combine (BN=48 covers fout=40) ----
    mma_gemm_kernel<48, true, false><<<ggrid, 256, SMEM_48>>>(
        hh, aggh, wh + WR_SW2, wh + WR_NW2, self_b2, neigh_b2, (float*)d_out, NN, NCLS, 0);
}